// round 9
// baseline (speedup 1.0000x reference)
#include <cuda_runtime.h>
#include <cuda_bf16.h>

#define RADIUS 3
constexpr int N_ = 2, C_ = 64, S_ = 4, H_ = 64, W_ = 44;
constexpr int P_  = H_ * W_;
constexpr int SP_ = S_ * P_;            // channel stride
constexpr int TILE_Y = 4;
constexpr int NTHREADS = 384;           // 12 warps

// Pixel-major bf16 tiles: one pixel = 64 ch * 2B = 128 B row, SW128 swizzled.
constexpr int F1ROWS = 10;              // y0-3 .. y0+6
constexpr int F1PX   = 56;              // n_x in [-3, 52] -> col = n_x + 3
constexpr int F0PX   = 48;              // x 0..43 staged, 44..47 junk (discarded rows)
constexpr int OFF_F1HI = 0;
constexpr int OFF_F1LO = OFF_F1HI + F1ROWS * F1PX * 128;   // 71680
constexpr int OFF_F0HI = OFF_F1LO + F1ROWS * F1PX * 128;   // 143360
constexpr int OFF_F0LO = OFF_F0HI + TILE_Y * F0PX * 128;   // 167936
constexpr int OFF_TAPS = OFF_F0LO + TILE_Y * F0PX * 128;   // 192512
constexpr int SMEM_BYTES = OFF_TAPS + 176 * 49 * 4;        // 227008

__device__ __forceinline__ int swz(int px, int byte) {
    return px * 128 + (byte ^ ((px & 7) << 4));
}

__device__ __forceinline__ void mma16816(float* c, const unsigned* a,
                                         unsigned b0, unsigned b1) {
    asm volatile(
        "mma.sync.aligned.m16n8k16.row.col.f32.bf16.bf16.f32 "
        "{%0,%1,%2,%3}, {%4,%5,%6,%7}, {%8,%9}, {%0,%1,%2,%3};"
        : "+f"(c[0]), "+f"(c[1]), "+f"(c[2]), "+f"(c[3])
        : "r"(a[0]), "r"(a[1]), "r"(a[2]), "r"(a[3]), "r"(b0), "r"(b1));
}

// Convert 8 fp32 (one ch-octet of one pixel) to hi/lo bf16, write 16B each.
__device__ __forceinline__ void stage_unit(char* smem, const float* __restrict__ f0g,
                                           const float* __restrict__ f1g,
                                           int base, int y0, int u) {
    const int slot = u >> 3, oct = u & 7;
    const float* src;
    int pxi, aHi, aLo;
    if (slot < 440) {                     // f1: 10 rows x 44 cols
        const int row = slot / 44, x = slot - row * 44;
        const int gy = y0 - RADIUS + row;
        if ((unsigned)gy >= (unsigned)H_) return;   // junk rows: dy masked
        src = f1g + base + gy * W_ + x;
        pxi = row * F1PX + x + RADIUS;
        aHi = OFF_F1HI; aLo = OFF_F1LO;
    } else {                              // f0: 4 rows x 44 cols
        const int t = slot - 440;
        const int row = t / 44, x = t - row * 44;
        src = f0g + base + (y0 + row) * W_ + x;
        pxi = row * F0PX + x;
        aHi = OFF_F0HI; aLo = OFF_F0LO;
    }
    const int chb = oct * 8;
    float v[8];
    #pragma unroll
    for (int j = 0; j < 8; ++j) v[j] = src[(chb + j) * SP_];
    unsigned hw[4], lw[4];
    #pragma unroll
    for (int j = 0; j < 4; ++j) {
        const float v0 = v[2 * j], v1 = v[2 * j + 1];
        const __nv_bfloat16 h0 = __float2bfloat16(v0);
        const __nv_bfloat16 h1 = __float2bfloat16(v1);
        const __nv_bfloat16 l0 = __float2bfloat16(v0 - __bfloat162float(h0));
        const __nv_bfloat16 l1 = __float2bfloat16(v1 - __bfloat162float(h1));
        hw[j] = (unsigned)__bfloat16_as_ushort(h0) |
                ((unsigned)__bfloat16_as_ushort(h1) << 16);   // even ch in low half
        lw[j] = (unsigned)__bfloat16_as_ushort(l0) |
                ((unsigned)__bfloat16_as_ushort(l1) << 16);
    }
    *(uint4*)(smem + aHi + swz(pxi, oct * 16)) = make_uint4(hw[0], hw[1], hw[2], hw[3]);
    *(uint4*)(smem + aLo + swz(pxi, oct * 16)) = make_uint4(lw[0], lw[1], lw[2], lw[3]);
}

__global__ __launch_bounds__(NTHREADS, 1)
void flow_kernel(const float* __restrict__ f0g, const float* __restrict__ f1g,
                 float* __restrict__ outg) {
    extern __shared__ char smem[];
    const int tid  = threadIdx.x;
    const int y0   = blockIdx.x * TILE_Y;
    const int b    = blockIdx.y;
    const int ni   = b >> 2;
    const int si   = b & 3;
    const int base = ((ni * C_) * S_ + si) * P_;

    // ---------------- staging: 616 px-slots x 8 ch-octets -------------------
    for (int u = tid; u < 2464; u += NTHREADS) {
        stage_unit(smem, f0g, f1g, base, y0, u);
        stage_unit(smem, f0g, f1g, base, y0, u + 2464);
    }
    __syncthreads();

    // ---------------- MMA phase: warp = (row yl, 16-px strip) ---------------
    {
        const int wid  = tid >> 5, lane = tid & 31;
        const int yl   = wid / 3, strip = wid % 3, xs = strip * 16;
        const int g    = lane >> 2;          // m-row / n within tile
        const int t4   = lane & 3;           // k-pair selector

        // Preload A fragments: {hi,lo} x 4 k-chunks, 4 regs each.
        unsigned a[8][4];
        const int apx = yl * F0PX + xs;
        #pragma unroll
        for (int hl = 0; hl < 2; ++hl) {
            const int ab = hl ? OFF_F0LO : OFF_F0HI;
            #pragma unroll
            for (int kc = 0; kc < 4; ++kc) {
                const int by = kc * 32 + t4 * 4;
                a[hl * 4 + kc][0] = *(const unsigned*)(smem + ab + swz(apx + g,     by));
                a[hl * 4 + kc][1] = *(const unsigned*)(smem + ab + swz(apx + g + 8, by));
                a[hl * 4 + kc][2] = *(const unsigned*)(smem + ab + swz(apx + g,     by + 16));
                a[hl * 4 + kc][3] = *(const unsigned*)(smem + ab + swz(apx + g + 8, by + 16));
            }
        }

        for (int dy = 0; dy < 7; ++dy) {
            const int gyr = y0 + yl + dy - RADIUS;
            if ((unsigned)gyr >= (unsigned)H_) continue;   // taps stay junk; masked
            const int row = yl + dy;                        // f1 smem row 0..9

            float acc[3][4];
            #pragma unroll
            for (int tt = 0; tt < 3; ++tt)
                #pragma unroll
                for (int r = 0; r < 4; ++r) acc[tt][r] = 0.0f;

            #pragma unroll
            for (int p = 0; p < 3; ++p) {    // hi*hi, hi*lo, lo*hi
                const int abase = (p == 2) ? 4 : 0;
                const int bb    = (p == 1) ? OFF_F1LO : OFF_F1HI;
                #pragma unroll
                for (int kc = 0; kc < 4; ++kc) {
                    const int by = kc * 32 + t4 * 4;
                    #pragma unroll
                    for (int tt = 0; tt < 3; ++tt) {
                        // n_x = xs-3+8*tt+g  ->  smem col n_x+3
                        const int pxb = row * F1PX + xs + 8 * tt + g;
                        const unsigned b0 = *(const unsigned*)(smem + bb + swz(pxb, by));
                        const unsigned b1 = *(const unsigned*)(smem + bb + swz(pxb, by + 16));
                        mma16816(acc[tt], a[abase + kc], b0, b1);
                    }
                }
            }

            // scatter the 7-diagonal band into taps[px][49]
            #pragma unroll
            for (int tt = 0; tt < 3; ++tt) {
                const int n0 = xs - RADIUS + 8 * tt + 2 * t4;
                #pragma unroll
                for (int cr = 0; cr < 4; ++cr) {
                    const int mrow = g + ((cr >= 2) ? 8 : 0);
                    const int px_x = xs + mrow;
                    const int n_x  = n0 + (cr & 1);
                    const int dx3  = n_x - px_x + RADIUS;
                    if (px_x < W_ && (unsigned)dx3 < 7u) {
                        *(float*)(smem + OFF_TAPS +
                                  (((yl * W_ + px_x) * 49) + dy * 7 + dx3) * 4) = acc[tt][cr];
                    }
                }
            }
        }
    }
    __syncthreads();

    // ---------------- epilogue: masked softmax + expected offset ------------
    if (tid < TILE_Y * W_) {
        const int yl = tid / W_;
        const int x  = tid - yl * W_;
        const int gy = y0 + yl;
        const float* tp = (const float*)(smem + OFF_TAPS) + tid * 49;

        float m = -1e30f;
        #pragma unroll
        for (int k = 0; k < 49; ++k) {
            const int dy = k / 7 - RADIUS, dx = k % 7 - RADIUS;
            const bool v = ((unsigned)(gy + dy) < (unsigned)H_) &&
                           ((unsigned)(x + dx) < (unsigned)W_);
            if (v) m = fmaxf(m, tp[k]);
        }
        float s = 0.0f, fx = 0.0f, fy = 0.0f;
        #pragma unroll
        for (int k = 0; k < 49; ++k) {
            const int dy = k / 7 - RADIUS, dx = k % 7 - RADIUS;
            const bool v = ((unsigned)(gy + dy) < (unsigned)H_) &&
                           ((unsigned)(x + dx) < (unsigned)W_);
            const float e = v ? __expf((tp[k] - m) * 0.125f) : 0.0f;
            s  += e;
            fx += e * (float)dx;
            fy += e * (float)dy;
        }
        const float inv = 1.0f / s;
        const int ob = ((ni * 2) * S_ + si) * P_ + gy * W_ + x;
        outg[ob]       = fx * inv;
        outg[ob + SP_] = fy * inv;
    }
}

extern "C" void kernel_launch(void* const* d_in, const int* in_sizes, int n_in,
                              void* d_out, int out_size) {
    const float* f0 = (const float*)d_in[0];
    const float* f1 = (const float*)d_in[1];
    float* out = (float*)d_out;

    cudaFuncSetAttribute(flow_kernel,
                         cudaFuncAttributeMaxDynamicSharedMemorySize, SMEM_BYTES);

    dim3 grid(H_ / TILE_Y, N_ * S_);
    flow_kernel<<<grid, NTHREADS, SMEM_BYTES>>>(f0, f1, out);
}